// round 7
// baseline (speedup 1.0000x reference)
#include <cuda_runtime.h>
#include <math.h>
#include <stdint.h>

#define Nn 64
#define T  512
#define Dd 512
#define Hh 512
#define G4 2048   // 4*H
#define NB 128    // persistent blocks (<=148 SMs, co-resident)

// ---------------- scratch (static device arrays) ----------------
__device__ __align__(128) float g_xW[(size_t)Nn * T * G4];   // [t][n][4H]
__device__ __align__(128) float g_h[2][Hh * Nn];             // ping-pong hidden, [hidx][n]
__device__ int g_gcnt[4];   // per-chunk-group arrival counters
__device__ int g_flag[4];   // per-chunk-group completed-step flags

// Packed dual-lane fp32 FMA (Blackwell FFMA2; only reachable via PTX f32x2)
__device__ __forceinline__ void fma2(unsigned long long& d,
                                     unsigned long long a,
                                     unsigned long long b) {
    asm("fma.rn.f32x2 %0, %1, %2, %0;" : "+l"(d) : "l"(a), "l"(b));
}
static __device__ __forceinline__ uint32_t s2u(const void* p) {
    return (uint32_t)__cvta_generic_to_shared(p);
}
static __device__ __forceinline__ void cpasync16(uint32_t dst, const void* src) {
    asm volatile("cp.async.cg.shared.global [%0], [%1], 16;" :: "r"(dst), "l"(src));
}
// warp-scope wait: lane 0 polls, broadcasts; no block sync needed
static __device__ __forceinline__ void wait_flag(const int* f, int target) {
    const int lane = threadIdx.x & 31;
    int v;
    do {
        v = 0;
        if (lane == 0) v = *(volatile const int*)f;
        v = __shfl_sync(0xffffffffu, v, 0);
    } while (v < target);
}

// ---------------------------------------------------------------------------
// GEMM 1 (round-3 version, best measured): xW = x @ Wx + b, relaid [t][n][4H].
// ---------------------------------------------------------------------------
__global__ __launch_bounds__(256) void gemm_xw(const float* __restrict__ x,
                                               const float* __restrict__ Wx,
                                               const float* __restrict__ b) {
    __shared__ float As[2][8][128];
    __shared__ float Bs[2][8][128];

    const int tid = threadIdx.x;
    const int tx = tid & 15;
    const int ty = tid >> 4;
    const int m0 = blockIdx.y * 128;
    const int n0 = blockIdx.x * 128;

    const int a_m = tid >> 1;
    const int a_k = (tid & 1) * 4;
    const int b_c = (tid & 31) * 4;
    const int b_k = tid >> 5;

    float acc[8][8];
#pragma unroll
    for (int i = 0; i < 8; i++)
#pragma unroll
        for (int j = 0; j < 8; j++) acc[i][j] = 0.f;

    float4 pa = *(const float4*)&x[(size_t)(m0 + a_m) * Dd + a_k];
    float4 pb = *(const float4*)&Wx[(size_t)b_k * G4 + n0 + b_c];
    As[0][a_k + 0][a_m] = pa.x;
    As[0][a_k + 1][a_m] = pa.y;
    As[0][a_k + 2][a_m] = pa.z;
    As[0][a_k + 3][a_m] = pa.w;
    *(float4*)&Bs[0][b_k][b_c] = pb;
    __syncthreads();

    const int NSTAGE = Dd / 8;
    for (int s = 0; s < NSTAGE; s++) {
        const int cur = s & 1;
        if (s + 1 < NSTAGE) {
            const int k0 = (s + 1) * 8;
            pa = *(const float4*)&x[(size_t)(m0 + a_m) * Dd + k0 + a_k];
            pb = *(const float4*)&Wx[(size_t)(k0 + b_k) * G4 + n0 + b_c];
        }
#pragma unroll
        for (int k = 0; k < 8; k++) {
            float4 a0 = *(float4*)&As[cur][k][ty * 8];
            float4 a1 = *(float4*)&As[cur][k][ty * 8 + 4];
            float4 b0 = *(float4*)&Bs[cur][k][tx * 8];
            float4 b1 = *(float4*)&Bs[cur][k][tx * 8 + 4];
            float av[8] = {a0.x, a0.y, a0.z, a0.w, a1.x, a1.y, a1.z, a1.w};
            float bv[8] = {b0.x, b0.y, b0.z, b0.w, b1.x, b1.y, b1.z, b1.w};
#pragma unroll
            for (int i = 0; i < 8; i++)
#pragma unroll
                for (int j = 0; j < 8; j++) acc[i][j] += av[i] * bv[j];
        }
        if (s + 1 < NSTAGE) {
            const int nxt = cur ^ 1;
            As[nxt][a_k + 0][a_m] = pa.x;
            As[nxt][a_k + 1][a_m] = pa.y;
            As[nxt][a_k + 2][a_m] = pa.z;
            As[nxt][a_k + 3][a_m] = pa.w;
            *(float4*)&Bs[nxt][b_k][b_c] = pb;
            __syncthreads();
        }
    }

    float4 bb0 = *(const float4*)&b[n0 + tx * 8];
    float4 bb1 = *(const float4*)&b[n0 + tx * 8 + 4];
#pragma unroll
    for (int i = 0; i < 8; i++) {
        int m = m0 + ty * 8 + i;
        int tt = m & (T - 1);
        int nn = m >> 9;
        size_t row = ((size_t)tt * Nn + nn) * G4 + n0 + tx * 8;
        *(float4*)&g_xW[row]     = make_float4(acc[i][0] + bb0.x, acc[i][1] + bb0.y,
                                               acc[i][2] + bb0.z, acc[i][3] + bb0.w);
        *(float4*)&g_xW[row + 4] = make_float4(acc[i][4] + bb1.x, acc[i][5] + bb1.y,
                                               acc[i][6] + bb1.z, acc[i][7] + bb1.w);
    }
}

// ---------------------------------------------------------------------------
// Init: g_h[0][h][n] = h0[n][h]; reset flag/counter state.
// ---------------------------------------------------------------------------
__global__ void lstm_init(const float* __restrict__ h0) {
    int i = blockIdx.x * blockDim.x + threadIdx.x;
    if (i < Nn * Hh) {
        int n = i & 63;
        int h = i >> 6;
        g_h[0][h * Nn + n] = h0[n * Hh + h];
    }
    if (i < 4) { g_gcnt[i] = 0; g_flag[i] = 0; }
}

// ---------------------------------------------------------------------------
// Persistent scan: r6 structure, monolithic grid barrier replaced by
// per-chunk producer flags. Block hb owns h units [hb*4, hb*4+4) = group hb>>5.
// Consumer waits flag[c] >= t just before staging chunk c (warp-local poll).
// ---------------------------------------------------------------------------
__global__ __launch_bounds__(256) void lstm_scan(const float* __restrict__ Wh,
                                                 float* __restrict__ out) {
    extern __shared__ float sm[];
    unsigned long long* wsd = (unsigned long long*)sm;   // [512][16] dup pairs (64KB)
    float* hfull  = sm + 512 * 16 * 2;                   // [512][64] (128KB)
    float* sacc   = hfull + 512 * 64;                    // [4][16][66]
    float* hstage = sacc + 4 * 16 * 66;                  // [64][4]

    const int tid = threadIdx.x;
    const int hb  = blockIdx.x;
    const int grp = hb >> 5;           // producer group of this block
    const int ks  = tid >> 6;          // k group 0..3
    const int r   = tid & 63;
    const int mq  = r & 15;            // batch group of 4
    const int cq  = r >> 4;            // col group of 4
    const int u_e = tid >> 6;          // epilogue: local hidden unit
    const int n_e = tid & 63;          // epilogue: batch

    // resident Wh slice, duplicated pairs {w,w}
    for (int idx = tid; idx < 512 * 16; idx += 256) {
        int k = idx >> 4;
        int c = idx & 15;
        int g = c >> 2;
        int u = c & 3;
        float w = Wh[(size_t)k * G4 + g * Hh + hb * 4 + u];
        ((float2*)wsd)[idx] = make_float2(w, w);
    }

    const uint32_t h_smem = s2u(hfull);
    float c_reg = 0.f;

    for (int t = 0; t < T; t++) {
        const float* hcur = g_h[t & 1];
        float*       hnxt = g_h[(t & 1) ^ 1];

        // prefetch this step's xW gate slice (independent of flags)
        const float* xwp = g_xW + ((size_t)t * Nn + n_e) * G4 + hb * 4 + u_e;
        float xw0 = xwp[0 * Hh];
        float xw1 = xwp[1 * Hh];
        float xw2 = xwp[2 * Hh];
        float xw3 = xwp[3 * Hh];

        // --- gated staging: wait for chunk c's producers, then issue 32KB ---
#pragma unroll
        for (int c = 0; c < 4; c++) {
            wait_flag(&g_flag[c], t);
#pragma unroll
            for (int p = 0; p < 8; p++) {
                uint32_t off = (uint32_t)c * 32768u + (uint32_t)(p * 256 + tid) * 16u;
                cpasync16(h_smem + off, (const char*)hcur + off);
            }
            asm volatile("cp.async.commit_group;");
        }

        // --- 4 overlapped GEMM phases ---
        unsigned long long acc00 = 0, acc01 = 0, acc10 = 0, acc11 = 0;
        unsigned long long acc20 = 0, acc21 = 0, acc30 = 0, acc31 = 0;

#define GEMM_PHASE(C, WG)                                                     \
        {                                                                     \
            asm volatile("cp.async.wait_group %0;" :: "n"(WG));               \
            __syncthreads();                                                  \
            const float* hbp = hfull + ((C) * 128 + ks * 32) * 64 + mq * 4;   \
            const unsigned long long* wbp =                                   \
                wsd + ((C) * 128 + ks * 32) * 16 + cq * 4;                    \
            _Pragma("unroll 8")                                               \
            for (int k = 0; k < 32; k++) {                                    \
                ulonglong2 a  = *(const ulonglong2*)(hbp + (size_t)k * 64);   \
                ulonglong2 w0 = *(const ulonglong2*)(wbp + k * 16);           \
                ulonglong2 w1 = *(const ulonglong2*)(wbp + k * 16 + 2);       \
                fma2(acc00, w0.x, a.x); fma2(acc01, w0.x, a.y);               \
                fma2(acc10, w0.y, a.x); fma2(acc11, w0.y, a.y);               \
                fma2(acc20, w1.x, a.x); fma2(acc21, w1.x, a.y);               \
                fma2(acc30, w1.y, a.x); fma2(acc31, w1.y, a.y);               \
            }                                                                 \
        }
        GEMM_PHASE(0, 3)
        GEMM_PHASE(1, 2)
        GEMM_PHASE(2, 1)
        GEMM_PHASE(3, 0)
#undef GEMM_PHASE

        // --- partials -> smem ---
        {
            float* p0 = &sacc[(ks * 16 + cq * 4 + 0) * 66 + mq * 4];
            float* p1 = &sacc[(ks * 16 + cq * 4 + 1) * 66 + mq * 4];
            float* p2 = &sacc[(ks * 16 + cq * 4 + 2) * 66 + mq * 4];
            float* p3 = &sacc[(ks * 16 + cq * 4 + 3) * 66 + mq * 4];
            *(unsigned long long*)(p0)     = acc00;
            *(unsigned long long*)(p0 + 2) = acc01;
            *(unsigned long long*)(p1)     = acc10;
            *(unsigned long long*)(p1 + 2) = acc11;
            *(unsigned long long*)(p2)     = acc20;
            *(unsigned long long*)(p2 + 2) = acc21;
            *(unsigned long long*)(p3)     = acc30;
            *(unsigned long long*)(p3 + 2) = acc31;
        }
        __syncthreads();

        // --- epilogue: thread handles (u_e, n_e) ---
        {
            float ag[4];
#pragma unroll
            for (int g = 0; g < 4; g++) {
                int c = g * 4 + u_e;
                ag[g] = sacc[(0 * 16 + c) * 66 + n_e]
                      + sacc[(1 * 16 + c) * 66 + n_e]
                      + sacc[(2 * 16 + c) * 66 + n_e]
                      + sacc[(3 * 16 + c) * 66 + n_e];
            }
            ag[0] += xw0; ag[1] += xw1; ag[2] += xw2; ag[3] += xw3;

            float iv = 1.f / (1.f + expf(-ag[0]));
            float fv = 1.f / (1.f + expf(-ag[1]));
            float ov = 1.f / (1.f + expf(-ag[2]));
            float gv = tanhf(ag[3]);

            c_reg = fv * c_reg + iv * gv;
            float hn = ov * tanhf(c_reg);

            hnxt[(hb * 4 + u_e) * Nn + n_e] = hn;   // coalesced
            hstage[n_e * 4 + u_e] = hn;
        }
        __syncthreads();   // hnxt + hstage complete block-wide

        // coalesced out write: out[n][t][hb*4..hb*4+3]
        if (tid < 64)
            *(float4*)&out[((size_t)tid * T + t) * Hh + hb * 4] =
                *(float4*)&hstage[tid * 4];

        // --- producer arrival: group counter; last of 32 releases the flag ---
        if (tid == 0) {
            __threadfence();
            int old = atomicAdd(&g_gcnt[grp], 1);
            if (old == 31) {
                g_gcnt[grp] = 0;
                __threadfence();
                *(volatile int*)&g_flag[grp] = t + 1;
            }
        }
        // no block-wide sync needed: next step's work is gated by flags,
        // smem reuse is protected by the per-phase syncthreads.
    }
}

// ---------------------------------------------------------------------------
// Launch
// ---------------------------------------------------------------------------
extern "C" void kernel_launch(void* const* d_in, const int* in_sizes, int n_in,
                              void* d_out, int out_size) {
    const float* x  = (const float*)d_in[0];
    const float* h0 = (const float*)d_in[1];
    const float* Wx = (const float*)d_in[2];
    const float* Wh = (const float*)d_in[3];
    const float* b  = (const float*)d_in[4];
    float* out = (float*)d_out;

    const int smem = (512 * 16 * 2 + 512 * 64 + 4 * 16 * 66 + 64 * 4) * sizeof(float);
    cudaFuncSetAttribute(lstm_scan, cudaFuncAttributeMaxDynamicSharedMemorySize, smem);

    dim3 g1(G4 / 128, (Nn * T) / 128);
    gemm_xw<<<g1, 256>>>(x, Wx, b);
    lstm_init<<<(Nn * Hh + 255) / 256, 256>>>(h0);
    lstm_scan<<<NB, 256, smem>>>(Wh, out);
}

// round 8
// speedup vs baseline: 1.1913x; 1.1913x over previous
#include <cuda_runtime.h>
#include <math.h>
#include <stdint.h>

#define Nn 64
#define T  512
#define Dd 512
#define Hh 512
#define G4 2048   // 4*H
#define NB 128    // persistent blocks
#define BPG 32    // blocks per batch group

// ---------------- scratch (static device arrays) ----------------
__device__ __align__(128) float g_xW[(size_t)Nn * T * G4];   // [t][n][4H]
__device__ __align__(128) float g_hd[2][Hh * Nn * 2];        // dup hidden: [k][n][2]
__device__ int g_gcnt[4];   // per-group arrival counters
__device__ int g_flag[4];   // per-group completed-step flags

// Packed dual-lane fp32 FMA (Blackwell FFMA2; only reachable via PTX f32x2)
__device__ __forceinline__ void fma2(unsigned long long& d,
                                     unsigned long long a,
                                     unsigned long long b) {
    asm("fma.rn.f32x2 %0, %1, %2, %0;" : "+l"(d) : "l"(a), "l"(b));
}
static __device__ __forceinline__ uint32_t s2u(const void* p) {
    return (uint32_t)__cvta_generic_to_shared(p);
}
static __device__ __forceinline__ void cpasync16(uint32_t dst, const void* src) {
    asm volatile("cp.async.cg.shared.global [%0], [%1], 16;" :: "r"(dst), "l"(src));
}

// ---------------------------------------------------------------------------
// GEMM 1 (r3 version, best measured): xW = x @ Wx + b, relaid [t][n][4H].
// ---------------------------------------------------------------------------
__global__ __launch_bounds__(256) void gemm_xw(const float* __restrict__ x,
                                               const float* __restrict__ Wx,
                                               const float* __restrict__ b) {
    __shared__ float As[2][8][128];
    __shared__ float Bs[2][8][128];

    const int tid = threadIdx.x;
    const int tx = tid & 15;
    const int ty = tid >> 4;
    const int m0 = blockIdx.y * 128;
    const int n0 = blockIdx.x * 128;

    const int a_m = tid >> 1;
    const int a_k = (tid & 1) * 4;
    const int b_c = (tid & 31) * 4;
    const int b_k = tid >> 5;

    float acc[8][8];
#pragma unroll
    for (int i = 0; i < 8; i++)
#pragma unroll
        for (int j = 0; j < 8; j++) acc[i][j] = 0.f;

    float4 pa = *(const float4*)&x[(size_t)(m0 + a_m) * Dd + a_k];
    float4 pb = *(const float4*)&Wx[(size_t)b_k * G4 + n0 + b_c];
    As[0][a_k + 0][a_m] = pa.x;
    As[0][a_k + 1][a_m] = pa.y;
    As[0][a_k + 2][a_m] = pa.z;
    As[0][a_k + 3][a_m] = pa.w;
    *(float4*)&Bs[0][b_k][b_c] = pb;
    __syncthreads();

    const int NSTAGE = Dd / 8;
    for (int s = 0; s < NSTAGE; s++) {
        const int cur = s & 1;
        if (s + 1 < NSTAGE) {
            const int k0 = (s + 1) * 8;
            pa = *(const float4*)&x[(size_t)(m0 + a_m) * Dd + k0 + a_k];
            pb = *(const float4*)&Wx[(size_t)(k0 + b_k) * G4 + n0 + b_c];
        }
#pragma unroll
        for (int k = 0; k < 8; k++) {
            float4 a0 = *(float4*)&As[cur][k][ty * 8];
            float4 a1 = *(float4*)&As[cur][k][ty * 8 + 4];
            float4 b0 = *(float4*)&Bs[cur][k][tx * 8];
            float4 b1 = *(float4*)&Bs[cur][k][tx * 8 + 4];
            float av[8] = {a0.x, a0.y, a0.z, a0.w, a1.x, a1.y, a1.z, a1.w};
            float bv[8] = {b0.x, b0.y, b0.z, b0.w, b1.x, b1.y, b1.z, b1.w};
#pragma unroll
            for (int i = 0; i < 8; i++)
#pragma unroll
                for (int j = 0; j < 8; j++) acc[i][j] += av[i] * bv[j];
        }
        if (s + 1 < NSTAGE) {
            const int nxt = cur ^ 1;
            As[nxt][a_k + 0][a_m] = pa.x;
            As[nxt][a_k + 1][a_m] = pa.y;
            As[nxt][a_k + 2][a_m] = pa.z;
            As[nxt][a_k + 3][a_m] = pa.w;
            *(float4*)&Bs[nxt][b_k][b_c] = pb;
            __syncthreads();
        }
    }

    float4 bb0 = *(const float4*)&b[n0 + tx * 8];
    float4 bb1 = *(const float4*)&b[n0 + tx * 8 + 4];
#pragma unroll
    for (int i = 0; i < 8; i++) {
        int m = m0 + ty * 8 + i;
        int tt = m & (T - 1);
        int nn = m >> 9;
        size_t row = ((size_t)tt * Nn + nn) * G4 + n0 + tx * 8;
        *(float4*)&g_xW[row]     = make_float4(acc[i][0] + bb0.x, acc[i][1] + bb0.y,
                                               acc[i][2] + bb0.z, acc[i][3] + bb0.w);
        *(float4*)&g_xW[row + 4] = make_float4(acc[i][4] + bb1.x, acc[i][5] + bb1.y,
                                               acc[i][6] + bb1.z, acc[i][7] + bb1.w);
    }
}

// ---------------------------------------------------------------------------
// Init: g_hd[0][k][n][2] = {h0[n][k], h0[n][k]}; reset counters/flags.
// ---------------------------------------------------------------------------
__global__ void lstm_init(const float* __restrict__ h0) {
    int i = blockIdx.x * blockDim.x + threadIdx.x;
    if (i < Nn * Hh) {
        int n = i & 63;
        int k = i >> 6;
        float v = h0[n * Hh + k];
        *(float2*)&g_hd[0][(k * Nn + n) * 2] = make_float2(v, v);
    }
    if (i < 4) { g_gcnt[i] = 0; g_flag[i] = 0; }
}

// ---------------------------------------------------------------------------
// Persistent scan, batch-partitioned. 4 independent groups of 32 blocks.
// Block (ng = hb>>5, hg = hb&31): batch rows [ng*16,+16), hidden [hg*16,+16).
// D[16n][64c] (c = u*4+g), k-split(4) inside the block.
// smem: W plain fp32 [512][64] 128KB | h-dup [512][32] 64KB | sacc [4][16][68].
// ---------------------------------------------------------------------------
__global__ __launch_bounds__(256) void lstm_scan(const float* __restrict__ Wh,
                                                 float* __restrict__ out) {
    extern __shared__ float sm[];
    float* ws   = sm;                    // [512][64]
    float* hs   = sm + 512 * 64;         // [512][32]  (16 n, duplicated)
    float* sacc = hs + 512 * 32;         // [4][16][68]

    const int tid = threadIdx.x;
    const int hb  = blockIdx.x;
    const int ng  = hb >> 5;            // batch group
    const int hg  = hb & 31;            // hidden group
    const int ks  = tid >> 6;           // k sub-slice 0..3
    const int r   = tid & 63;
    const int mq  = r & 7;              // n-pair index (n = 2mq, 2mq+1)
    const int cq  = r >> 3;             // c-octet index (c = cq*8..+8)
    const int n_e = tid & 15;           // epilogue: local batch
    const int u_e = tid >> 4;           // epilogue: local hidden unit

    // resident W slice: ws[k][u*4+g] = Wh[k][g*512 + hg*16 + u]
    for (int idx = tid; idx < 512 * 64; idx += 256) {
        int k = idx >> 6;
        int c = idx & 63;
        int u = c >> 2;
        int g = c & 3;
        ws[idx] = Wh[(size_t)k * G4 + g * Hh + hg * 16 + u];
    }

    const uint32_t h_smem = s2u(hs);
    float c_reg = 0.f;

    for (int t = 0; t < T; t++) {
        const int cur = t & 1;
        const float* hsrc = g_hd[cur];          // [k][64n][2]
        float*       hdst = g_hd[cur ^ 1];

        // prefetch this step's xW gate slice
        const int gn = ng * 16 + n_e;
        const float* xwp = g_xW + ((size_t)t * Nn + gn) * G4 + hg * 16 + u_e;
        float xw0 = xwp[0 * Hh];
        float xw1 = xwp[1 * Hh];
        float xw2 = xwp[2 * Hh];
        float xw3 = xwp[3 * Hh];

        // --- stage dup-h slice: 4 chunks of 16KB (128 k x 128B), one group each
        //     src row k: 128B at hsrc + k*512B + ng*128B ---
#pragma unroll
        for (int c = 0; c < 4; c++) {
#pragma unroll
            for (int q = 0; q < 4; q++) {
                int id  = q * 256 + tid;          // 0..1023
                int k_l = id >> 3;                // 0..127
                int prt = id & 7;                 // 16B part of 128B row
                uint32_t dst = h_smem + (uint32_t)((c * 128 + k_l) * 128 + prt * 16);
                const char* src = (const char*)hsrc +
                                  (size_t)(c * 128 + k_l) * 512 + ng * 128 + prt * 16;
                cpasync16(dst, src);
            }
            asm volatile("cp.async.commit_group;");
        }

        // --- 4 overlapped GEMM phases; ks covers 32 k of each chunk ---
        unsigned long long a00 = 0, a01 = 0, a02 = 0, a03 = 0;
        unsigned long long a10 = 0, a11 = 0, a12 = 0, a13 = 0;

#define GEMM_PHASE(C, WG)                                                     \
        {                                                                     \
            asm volatile("cp.async.wait_group %0;" :: "n"(WG));               \
            __syncthreads();                                                  \
            const float* hbp = hs + ((C) * 128 + ks * 32) * 32 + mq * 4;      \
            const float* wbp = ws + ((C) * 128 + ks * 32) * 64 + cq * 8;      \
            _Pragma("unroll 8")                                               \
            for (int k = 0; k < 32; k++) {                                    \
                ulonglong2 hd = *(const ulonglong2*)(hbp + k * 32);           \
                ulonglong2 w0 = *(const ulonglong2*)(wbp + k * 64);           \
                ulonglong2 w1 = *(const ulonglong2*)(wbp + k * 64 + 4);       \
                fma2(a00, hd.x, w0.x); fma2(a01, hd.x, w0.y);                 \
                fma2(a02, hd.x, w1.x); fma2(a03, hd.x, w1.y);                 \
                fma2(a10, hd.y, w0.x); fma2(a11, hd.y, w0.y);                 \
                fma2(a12, hd.y, w1.x); fma2(a13, hd.y, w1.y);                 \
            }                                                                 \
        }
        GEMM_PHASE(0, 3)
        GEMM_PHASE(1, 2)
        GEMM_PHASE(2, 1)
        GEMM_PHASE(3, 0)
#undef GEMM_PHASE

        // --- partials -> sacc[ks][n][c] (pad 68) ---
        {
            float* p0 = &sacc[(ks * 16 + mq * 2 + 0) * 68 + cq * 8];
            float* p1 = &sacc[(ks * 16 + mq * 2 + 1) * 68 + cq * 8];
            ((unsigned long long*)p0)[0] = a00;
            ((unsigned long long*)p0)[1] = a01;
            ((unsigned long long*)p0)[2] = a02;
            ((unsigned long long*)p0)[3] = a03;
            ((unsigned long long*)p1)[0] = a10;
            ((unsigned long long*)p1)[1] = a11;
            ((unsigned long long*)p1)[2] = a12;
            ((unsigned long long*)p1)[3] = a13;
        }
        __syncthreads();

        // --- epilogue: thread handles (n_e, u_e); gates at c = u_e*4 + g ---
        {
            float4 s0 = *(float4*)&sacc[(0 * 16 + n_e) * 68 + u_e * 4];
            float4 s1 = *(float4*)&sacc[(1 * 16 + n_e) * 68 + u_e * 4];
            float4 s2 = *(float4*)&sacc[(2 * 16 + n_e) * 68 + u_e * 4];
            float4 s3 = *(float4*)&sacc[(3 * 16 + n_e) * 68 + u_e * 4];
            float ai = s0.x + s1.x + s2.x + s3.x + xw0;
            float af = s0.y + s1.y + s2.y + s3.y + xw1;
            float ao = s0.z + s1.z + s2.z + s3.z + xw2;
            float ag = s0.w + s1.w + s2.w + s3.w + xw3;

            float iv = 1.f / (1.f + expf(-ai));
            float fv = 1.f / (1.f + expf(-af));
            float ov = 1.f / (1.f + expf(-ao));
            float gv = tanhf(ag);

            c_reg = fv * c_reg + iv * gv;
            float hn = ov * tanhf(c_reg);

            const int gk = hg * 16 + u_e;
            // dup write, coalesced along n within 16-lane groups
            *(float2*)&hdst[(gk * Nn + gn) * 2] = make_float2(hn, hn);
            out[((size_t)gn * T + t) * Hh + gk] = hn;
        }
        __syncthreads();

        // --- per-group barrier (32 blocks) ---
        if (tid == 0) {
            __threadfence();
            int v = atomicAdd(&g_gcnt[ng], 1);
            if (v == BPG - 1) {
                g_gcnt[ng] = 0;
                __threadfence();
                *(volatile int*)&g_flag[ng] = t + 1;
            } else {
                while (*(volatile int*)&g_flag[ng] < t + 1) { }
            }
            __threadfence();
        }
        __syncthreads();
    }
}

// ---------------------------------------------------------------------------
// Launch
// ---------------------------------------------------------------------------
extern "C" void kernel_launch(void* const* d_in, const int* in_sizes, int n_in,
                              void* d_out, int out_size) {
    const float* x  = (const float*)d_in[0];
    const float* h0 = (const float*)d_in[1];
    const float* Wx = (const float*)d_in[2];
    const float* Wh = (const float*)d_in[3];
    const float* b  = (const float*)d_in[4];
    float* out = (float*)d_out;

    const int smem = (512 * 64 + 512 * 32 + 4 * 16 * 68) * sizeof(float);
    cudaFuncSetAttribute(lstm_scan, cudaFuncAttributeMaxDynamicSharedMemorySize, smem);

    dim3 g1(G4 / 128, (Nn * T) / 128);
    gemm_xw<<<g1, 256>>>(x, Wx, b);
    lstm_init<<<(Nn * Hh + 255) / 256, 256>>>(h0);
    lstm_scan<<<NB, 256, smem>>>(Wh, out);
}